// round 17
// baseline (speedup 1.0000x reference)
#include <cuda_runtime.h>
#include <cuda_bf16.h>
#include <cstdint>

#define T_STEPS 1024
#define Hn      100
#define KPAD    112            // 7 k16 steps; k 100..111 zero
#define ASTR    240            // A/B row stride bytes (60 words: bank-clean)
#define NTHREADS 384           // 12 warps -> 3/SMSP -> reg cap 170
#define NBLOCKS 128
#define BTOT    512
#define BB      4
#define GSTR    10             // gates row stride in floats

// dynamic smem map
#define SM_A_HI 0
#define A_BYTES (400 * ASTR)                 // 96000
#define SM_A_LO (SM_A_HI + A_BYTES)          // 96000
#define SM_BT   (SM_A_LO + A_BYTES)          // 192000 (8 rows x ASTR)
#define SM_GS   (SM_BT + 8 * ASTR)           // 193920 (400 x GSTR floats)
#define SM_WIH  (SM_GS + 400 * GSTR * 4)     // 209920
#define SM_BIAS (SM_WIH + Hn * 16)           // 211520
#define SMEM_SIZE (SM_BIAS + Hn * 16)        // 213120

__device__ float g_hscr[T_STEPS][Hn][BTOT];

__device__ __forceinline__ float ex2a(float x) {
    float y; asm("ex2.approx.ftz.f32 %0, %1;" : "=f"(y) : "f"(x)); return y;
}
__device__ __forceinline__ float rcpa(float x) {
    float y; asm("rcp.approx.ftz.f32 %0, %1;" : "=f"(y) : "f"(x)); return y;
}
__device__ __forceinline__ float sigm(float x) {
    return rcpa(1.0f + ex2a(-1.4426950408889634f * x));
}
__device__ __forceinline__ float tanhx(float x) {
    return fmaf(2.0f, rcpa(1.0f + ex2a(-2.8853900817779268f * x)), -1.0f);
}

// m16n8k16 row.col f32.bf16.bf16.f32 — baseline PTX (sm_80+)
#define MMA(d0,d1,d2,d3,a0,a1,a2,a3,b0,b1)                                  \
    asm volatile("mma.sync.aligned.m16n8k16.row.col.f32.bf16.bf16.f32 "     \
                 "{%0,%1,%2,%3}, {%4,%5,%6,%7}, {%8,%9}, {%0,%1,%2,%3};"    \
                 : "+f"(d0), "+f"(d1), "+f"(d2), "+f"(d3)                   \
                 : "r"(a0), "r"(a1), "r"(a2), "r"(a3), "r"(b0), "r"(b1))

__device__ __forceinline__ float cell_step(const float* gS, const float4* wihS,
                                           const float4* biasS, int n, int b,
                                           float x, float& c) {
    const float4 wv = wihS[n], bv = biasS[n];
    float gi = gS[n * GSTR + b]         + gS[n * GSTR + b + 4];
    float gf = gS[(100 + n) * GSTR + b] + gS[(100 + n) * GSTR + b + 4];
    float gg = gS[(200 + n) * GSTR + b] + gS[(200 + n) * GSTR + b + 4];
    float go = gS[(300 + n) * GSTR + b] + gS[(300 + n) * GSTR + b + 4];
    gi = fmaf(x, wv.x, gi + bv.x);
    gf = fmaf(x, wv.y, gf + bv.y);
    gg = fmaf(x, wv.z, gg + bv.z);
    go = fmaf(x, wv.w, go + bv.w);
    c = fmaf(sigm(gf), c, sigm(gi) * tanhx(gg));
    return sigm(go) * tanhx(c);
}

// Tensor-core step GEMM: D[400,8] = W[400,112] @ B[8,112]^T, bf16 2-term split.
// 50 tile-passes (25 m16 tiles x {Whi, Wlo}). Warp w (of 12) keeps tile-passes
// {4w..4w+3} = tiles {2w, 2w+1} x {hi, lo} RESIDENT in regs (112). hi passes
// fold (shfl xor2) into gS cols 0-3; lo passes into cols 4-7; cell gate =
// gS[b] + gS[b+4]. Tile 24 (rows 384-399) from SMEM by warps 0 (hi) / 1 (lo).
__global__ void __launch_bounds__(NTHREADS, 1)
lstm_mma_kernel(const float* __restrict__ input,
                const float* __restrict__ W_ih,
                const float* __restrict__ W_hh,
                const float* __restrict__ b_ih,
                const float* __restrict__ b_hh)
{
    extern __shared__ char smem[];
    const int tid = threadIdx.x;
    const int wid = tid >> 5;
    const int lane = tid & 31;
    const int lr = lane >> 2;          // fragment row-in-group
    const int lc = lane & 3;           // fragment col-group
    const int bbase = blockIdx.x * BB;

    // ---- build A_hi / A_lo (bf16 split of W_hh, row-major, k padded) ----
    for (int idx = tid; idx < 400 * KPAD; idx += NTHREADS) {
        const int r = idx / KPAD, k = idx - r * KPAD;
        const float wv = (k < Hn) ? W_hh[r * Hn + k] : 0.0f;
        const __nv_bfloat16 hi = __float2bfloat16(wv);
        const __nv_bfloat16 lo = __float2bfloat16(wv - __bfloat162float(hi));
        *(__nv_bfloat16*)(smem + SM_A_HI + r * ASTR + k * 2) = hi;
        *(__nv_bfloat16*)(smem + SM_A_LO + r * ASTR + k * 2) = lo;
    }
    for (int idx = tid; idx < 8 * ASTR / 4; idx += NTHREADS)
        ((uint32_t*)(smem + SM_BT))[idx] = 0u;
    for (int idx = tid; idx < 400 * GSTR; idx += NTHREADS)
        ((float*)(smem + SM_GS))[idx] = 0.0f;
    if (tid < Hn) {
        const int n = tid;
        *(float4*)(smem + SM_WIH + n * 16) = make_float4(
            W_ih[n], W_ih[Hn + n], W_ih[2 * Hn + n], W_ih[3 * Hn + n]);
        *(float4*)(smem + SM_BIAS + n * 16) = make_float4(
            b_ih[n] + b_hh[n], b_ih[Hn + n] + b_hh[Hn + n],
            b_ih[2 * Hn + n] + b_hh[2 * Hn + n],
            b_ih[3 * Hn + n] + b_hh[3 * Hn + n]);
    }
    __syncthreads();

    // ---- resident A fragments: tile-pass j -> tile 2*wid+(j>>1), pass j&1 ----
    uint32_t af[4][7][4];   // 112 regs
    #pragma unroll
    for (int j = 0; j < 4; ++j) {
        const int tile = 2 * wid + (j >> 1);
        const int pass = j & 1;
        #pragma unroll
        for (int ks = 0; ks < 7; ++ks) {
            const char* bp = smem + (pass ? SM_A_LO : SM_A_HI) +
                (tile * 16 + lr) * ASTR + lc * 4 + 32 * ks;
            af[j][ks][0] = *(const uint32_t*)(bp);
            af[j][ks][1] = *(const uint32_t*)(bp + 8 * ASTR);
            af[j][ks][2] = *(const uint32_t*)(bp + 16);
            af[j][ks][3] = *(const uint32_t*)(bp + 8 * ASTR + 16);
        }
    }

    // epilogue cells: cell1 = tid (n=tid>>2, b=tid&3); cell2 = tid+384 (tid<16)
    const int n1 = tid >> 2, b1 = tid & 3;
    const int n2 = 96 + n1;            // only meaningful for tid<16
    const bool has2 = (tid < 16);
    float cs1 = 0.0f, cs2 = 0.0f;
    float* gS = (float*)(smem + SM_GS);
    const float4* wihS = (const float4*)(smem + SM_WIH);
    const float4* biasS = (const float4*)(smem + SM_BIAS);
    const float* __restrict__ xp = input + (bbase + b1) * T_STEPS;
    const char* btBase = smem + SM_BT + lr * ASTR + lc * 4;

    for (int t = 0; t < T_STEPS; ++t) {
        const float xv = xp[t];   // issued early; consumed in the epilogue

        // ---- B fragments (lane lr = B-col, lc*2 = k base) ----
        uint32_t bf0[7], bf1[7];
        #pragma unroll
        for (int ks = 0; ks < 7; ++ks) {
            bf0[ks] = *(const uint32_t*)(btBase + 32 * ks);
            bf1[ks] = *(const uint32_t*)(btBase + 32 * ks + 16);
        }
        // ---- 4 independent 7-deep MMA chains per warp ----
        #pragma unroll
        for (int j = 0; j < 4; ++j) {
            float d0 = 0.f, d1 = 0.f, d2 = 0.f, d3 = 0.f;
            #pragma unroll
            for (int ks = 0; ks < 7; ++ks)
                MMA(d0, d1, d2, d3, af[j][ks][0], af[j][ks][1],
                    af[j][ks][2], af[j][ks][3], bf0[ks], bf1[ks]);
            const float f0 = d0 + __shfl_xor_sync(0xffffffffu, d0, 2);
            const float f1 = d1 + __shfl_xor_sync(0xffffffffu, d1, 2);
            const float f2 = d2 + __shfl_xor_sync(0xffffffffu, d2, 2);
            const float f3 = d3 + __shfl_xor_sync(0xffffffffu, d3, 2);
            if (lc < 2) {
                const int row = (2 * wid + (j >> 1)) * 16 + lr;
                const int co = (j & 1) * 4 + lc * 2;  // hi -> 0-3, lo -> 4-7
                *(float2*)(gS + row * GSTR + co) = make_float2(f0, f1);
                *(float2*)(gS + (row + 8) * GSTR + co) = make_float2(f2, f3);
            }
        }
        // ---- tile 24 (rows 384-399): warp 0 = hi, warp 1 = lo, from SMEM ----
        if (wid < 2) {
            float d0 = 0.f, d1 = 0.f, d2 = 0.f, d3 = 0.f;
            const char* ap = smem + (wid ? SM_A_LO : SM_A_HI) +
                             (384 + lr) * ASTR + lc * 4;
            #pragma unroll
            for (int ks = 0; ks < 7; ++ks) {
                const uint32_t a0 = *(const uint32_t*)(ap + 32 * ks);
                const uint32_t a1 = *(const uint32_t*)(ap + 32 * ks + 8 * ASTR);
                const uint32_t a2 = *(const uint32_t*)(ap + 32 * ks + 16);
                const uint32_t a3 = *(const uint32_t*)(ap + 32 * ks + 8 * ASTR + 16);
                MMA(d0, d1, d2, d3, a0, a1, a2, a3, bf0[ks], bf1[ks]);
            }
            const float f0 = d0 + __shfl_xor_sync(0xffffffffu, d0, 2);
            const float f1 = d1 + __shfl_xor_sync(0xffffffffu, d1, 2);
            const float f2 = d2 + __shfl_xor_sync(0xffffffffu, d2, 2);
            const float f3 = d3 + __shfl_xor_sync(0xffffffffu, d3, 2);
            if (lc < 2) {
                const int row = 384 + lr;
                const int co = lc * 2 + wid * 4;
                *(float2*)(gS + row * GSTR + co) = make_float2(f0, f1);
                *(float2*)(gS + (row + 8) * GSTR + co) = make_float2(f2, f3);
            }
        }
        __syncthreads();

        // ---- epilogue: gates -> (c,h); rebuild Bt; stream h ----
        {
            const float h1 = cell_step(gS, wihS, biasS, n1, b1, xv, cs1);
            const __nv_bfloat16 h1h = __float2bfloat16(h1);
            const __nv_bfloat16 h1l =
                __float2bfloat16(h1 - __bfloat162float(h1h));
            *(__nv_bfloat16*)(smem + SM_BT + b1 * ASTR + n1 * 2) = h1h;
            *(__nv_bfloat16*)(smem + SM_BT + (b1 + 4) * ASTR + n1 * 2) = h1l;
            g_hscr[t][n1][bbase + b1] = h1;
            if (has2) {
                const float h2 = cell_step(gS, wihS, biasS, n2, b1, xv, cs2);
                const __nv_bfloat16 h2h = __float2bfloat16(h2);
                const __nv_bfloat16 h2l =
                    __float2bfloat16(h2 - __bfloat162float(h2h));
                *(__nv_bfloat16*)(smem + SM_BT + b1 * ASTR + n2 * 2) = h2h;
                *(__nv_bfloat16*)(smem + SM_BT + (b1 + 4) * ASTR + n2 * 2) = h2l;
                g_hscr[t][n2][bbase + b1] = h2;
            }
        }
        __syncthreads();
    }
}

// Output projection: DRAM-bound (measured ~40us @ 68% DRAM).
__global__ void __launch_bounds__(BTOT, 2)
out_proj_kernel(const float* __restrict__ W_out,
                const float* __restrict__ b_out,
                float* __restrict__ out)
{
    const int t = blockIdx.x;
    const int b = threadIdx.x;
    float acc = b_out[0];
    const float* __restrict__ hp = &g_hscr[t][0][b];
    #pragma unroll 5
    for (int nn = 0; nn < Hn; ++nn)
        acc = fmaf(W_out[nn], hp[(size_t)nn * BTOT], acc);
    out[b * T_STEPS + t] = acc;
}

extern "C" void kernel_launch(void* const* d_in, const int* in_sizes, int n_in,
                              void* d_out, int out_size) {
    (void)in_sizes; (void)n_in; (void)out_size;
    const float* input = (const float*)d_in[0];
    const float* W_ih  = (const float*)d_in[1];
    const float* W_hh  = (const float*)d_in[2];
    const float* b_ih  = (const float*)d_in[3];
    const float* b_hh  = (const float*)d_in[4];
    const float* W_out = (const float*)d_in[5];
    const float* b_out = (const float*)d_in[6];
    float* out = (float*)d_out;

    cudaFuncSetAttribute(lstm_mma_kernel,
                         cudaFuncAttributeMaxDynamicSharedMemorySize, SMEM_SIZE);
    lstm_mma_kernel<<<NBLOCKS, NTHREADS, SMEM_SIZE>>>(
        input, W_ih, W_hh, b_ih, b_hh);
    out_proj_kernel<<<T_STEPS, BTOT>>>(W_out, b_out, out);
}